// round 11
// baseline (speedup 1.0000x reference)
#include <cuda_runtime.h>

// L0 contraction: out[b,n] = cg_n * sum_{m in deg-block n} sphc[b,m]^2
// Row of 15 floats: [0:3) deg1, [3:8) deg2, [8:15) deg3.
// Traffic floor: 240MB read + 48MB write = 288MB (~36us @ 8TB/s spec).
// R11: R10 geometry (160-row tiles, 9.6KB smem, 16 blk/SM = 64 warps,
//      __ldcs loads, direct __stcs stores) but with PER-WARP tiles:
//      each warp owns 40 rows (2400B, 16B-aligned region) and syncs with
//      __syncwarp() only -> warps are independent pipelines, no block
//      barrier, no cross-warp wait on straggling loads.

constexpr int THREADS = 128;
constexpr int ROWS_PER_BLOCK = 160;
constexpr int ROWS_PER_WARP = 40;             // 40*15 = 600 floats = 150 float4
constexpr int M = 15;
constexpr int WARP_F4 = ROWS_PER_WARP * M / 4;  // 150

__global__ __launch_bounds__(THREADS, 16) void l0_contraction_kernel(
    const float* __restrict__ sphc,
    const float* __restrict__ cg,
    float* __restrict__ out,
    int B)
{
    __shared__ float s_in[ROWS_PER_BLOCK * M];   // 9600 B

    const float c0 = __ldg(cg + 0);  // 1/sqrt(3)
    const float c1 = __ldg(cg + 3);  // 1/sqrt(5)
    const float c2 = __ldg(cg + 8);  // 1/sqrt(7)

    const long long row0 = (long long)blockIdx.x * ROWS_PER_BLOCK;
    const int tid  = threadIdx.x;
    const int wid  = tid >> 5;
    const int lane = tid & 31;
    const int nrows = (int)min((long long)ROWS_PER_BLOCK, (long long)B - row0);

    if (nrows == ROWS_PER_BLOCK) {
        // ---- full tile, per-warp independent pipeline ----
        // Warp w owns rows [w*40, w*40+40): 2400B of input at a 16B-aligned
        // offset (w*2400), 150 float4 loaded by 32 lanes.
        const long long wrow0 = row0 + (long long)wid * ROWS_PER_WARP;
        const float4* gin = reinterpret_cast<const float4*>(sphc + wrow0 * M);
        float4* s4 = reinterpret_cast<float4*>(s_in + wid * ROWS_PER_WARP * M);

        #pragma unroll
        for (int i = 0; i < (WARP_F4 + 31) / 32; i++) {   // 5 iters (last ragged)
            const int idx = lane + i * 32;
            if (idx < WARP_F4) s4[idx] = __ldcs(gin + idx);
        }
        __syncwarp();

        const float* wbuf = s_in + wid * ROWS_PER_WARP * M;
        // 40 rows over 32 lanes: row=lane for all, row=32+lane for lane<8.
        #pragma unroll
        for (int j = 0; j < 2; j++) {
            const int r = lane + j * 32;
            if (r < ROWS_PER_WARP) {
                const float* x = wbuf + r * M;   // stride 15: conflict-free
                float a = x[0]*x[0] + x[1]*x[1] + x[2]*x[2];
                float b = x[3]*x[3] + x[4]*x[4] + x[5]*x[5] + x[6]*x[6] + x[7]*x[7];
                float c = x[8]*x[8] + x[9]*x[9] + x[10]*x[10] + x[11]*x[11]
                        + x[12]*x[12] + x[13]*x[13] + x[14]*x[14];
                float* o = out + (wrow0 + r) * 3;
                __stcs(o + 0, a * c0);
                __stcs(o + 1, b * c1);
                __stcs(o + 2, c * c2);
            }
        }
    } else {
        // ---- tail tile: scalar, guarded, block-cooperative ----
        const float* gin = sphc + row0 * M;
        const int nf = nrows * M;
        for (int i = tid; i < nf; i += THREADS) s_in[i] = gin[i];
        __syncthreads();

        for (int r = tid; r < nrows; r += THREADS) {
            const float* x = s_in + r * M;
            float a = x[0]*x[0] + x[1]*x[1] + x[2]*x[2];
            float b = x[3]*x[3] + x[4]*x[4] + x[5]*x[5] + x[6]*x[6] + x[7]*x[7];
            float c = x[8]*x[8] + x[9]*x[9] + x[10]*x[10] + x[11]*x[11]
                    + x[12]*x[12] + x[13]*x[13] + x[14]*x[14];
            float* o = out + (row0 + r) * 3;
            o[0] = a * c0;
            o[1] = b * c1;
            o[2] = c * c2;
        }
    }
}

extern "C" void kernel_launch(void* const* d_in, const int* in_sizes, int n_in,
                              void* d_out, int out_size) {
    const float* sphc = (const float*)d_in[0];
    const float* cg   = (const float*)d_in[1];
    // d_in[2] = segment_ids (structure is compile-time: 3/5/7 blocks)
    float* out = (float*)d_out;

    const int B = in_sizes[0] / M;  // 4,000,000
    const int grid = (B + ROWS_PER_BLOCK - 1) / ROWS_PER_BLOCK;  // 25000
    l0_contraction_kernel<<<grid, THREADS>>>(sphc, cg, out, B);
}

// round 12
// speedup vs baseline: 1.0384x; 1.0384x over previous
#include <cuda_runtime.h>

// L0 contraction: out[b,n] = cg_n * sum_{m in deg-block n} sphc[b,m]^2
// Row of 15 floats: [0:3) deg1, [3:8) deg2, [8:15) deg3.
// Traffic floor: 240MB read + 48MB write = 288MB (~36us @ 8TB/s spec).
// R12: R10 architecture (block-staged __ldcs loads, one barrier, direct
//      __stcs row stores) at 192-row tiles. Without the old s_out buffer
//      smem is 11.52KB/block -> (11.52+1)*16 = 200KB <= 228KB carveout and
//      regs=32 -> 128*32*16 = 64K regfile exact fit: 16 blocks/SM (64
//      warps) preserved with +20% bytes per barrier vs 160-row R10.

constexpr int THREADS = 128;
constexpr int ROWS_PER_BLOCK = 192;
constexpr int M = 15;
constexpr int NV = ROWS_PER_BLOCK * M / 4;   // 720 float4 in

__global__ __launch_bounds__(THREADS, 16) void l0_contraction_kernel(
    const float* __restrict__ sphc,
    const float* __restrict__ cg,
    float* __restrict__ out,
    int B)
{
    __shared__ float s_in[ROWS_PER_BLOCK * M];   // 11520 B

    const float c0 = __ldg(cg + 0);  // 1/sqrt(3)
    const float c1 = __ldg(cg + 3);  // 1/sqrt(5)
    const float c2 = __ldg(cg + 8);  // 1/sqrt(7)

    const long long row0 = (long long)blockIdx.x * ROWS_PER_BLOCK;
    const int tid = threadIdx.x;
    const int nrows = (int)min((long long)ROWS_PER_BLOCK, (long long)B - row0);

    if (nrows == ROWS_PER_BLOCK) {
        // ---- full tile ----
        // 192 rows * 60B = 11520B per tile; tile base 16B-aligned.
        const float4* gin = reinterpret_cast<const float4*>(sphc + row0 * M);
        float4* s4 = reinterpret_cast<float4*>(s_in);
        #pragma unroll
        for (int i = 0; i < (NV + THREADS - 1) / THREADS; i++) {  // 6 iters (last 80 thr)
            const int idx = tid + i * THREADS;
            if (idx < NV) s4[idx] = __ldcs(gin + idx);  // evict-first stream
        }
        __syncthreads();

        // 192 rows over 128 threads: iter0 all lanes, iter1 lanes < 64.
        // Direct stores: thread writes 3 consecutive floats; warp covers
        // 384 contiguous bytes -> fully-utilized sectors.
        #pragma unroll
        for (int j = 0; j < 2; j++) {
            const int r = tid + j * THREADS;
            if (r < ROWS_PER_BLOCK) {
                const float* x = s_in + r * M;   // stride 15: conflict-free
                float a = x[0]*x[0] + x[1]*x[1] + x[2]*x[2];
                float b = x[3]*x[3] + x[4]*x[4] + x[5]*x[5] + x[6]*x[6] + x[7]*x[7];
                float c = x[8]*x[8] + x[9]*x[9] + x[10]*x[10] + x[11]*x[11]
                        + x[12]*x[12] + x[13]*x[13] + x[14]*x[14];
                float* o = out + (row0 + r) * 3;
                __stcs(o + 0, a * c0);
                __stcs(o + 1, b * c1);
                __stcs(o + 2, c * c2);
            }
        }
    } else {
        // ---- tail tile: scalar, guarded ----
        const float* gin = sphc + row0 * M;
        const int nf = nrows * M;
        for (int i = tid; i < nf; i += THREADS) s_in[i] = gin[i];
        __syncthreads();

        for (int r = tid; r < nrows; r += THREADS) {
            const float* x = s_in + r * M;
            float a = x[0]*x[0] + x[1]*x[1] + x[2]*x[2];
            float b = x[3]*x[3] + x[4]*x[4] + x[5]*x[5] + x[6]*x[6] + x[7]*x[7];
            float c = x[8]*x[8] + x[9]*x[9] + x[10]*x[10] + x[11]*x[11]
                    + x[12]*x[12] + x[13]*x[13] + x[14]*x[14];
            float* o = out + (row0 + r) * 3;
            o[0] = a * c0;
            o[1] = b * c1;
            o[2] = c * c2;
        }
    }
}

extern "C" void kernel_launch(void* const* d_in, const int* in_sizes, int n_in,
                              void* d_out, int out_size) {
    const float* sphc = (const float*)d_in[0];
    const float* cg   = (const float*)d_in[1];
    // d_in[2] = segment_ids (structure is compile-time: 3/5/7 blocks)
    float* out = (float*)d_out;

    const int B = in_sizes[0] / M;  // 4,000,000
    const int grid = (B + ROWS_PER_BLOCK - 1) / ROWS_PER_BLOCK;  // 20834
    l0_contraction_kernel<<<grid, THREADS>>>(sphc, cg, out, B);
}

// round 13
// speedup vs baseline: 1.0391x; 1.0007x over previous
#include <cuda_runtime.h>

// L0 contraction: out[b,n] = cg_n * sum_{m in deg-block n} sphc[b,m]^2
// Row of 15 floats: [0:3) deg1, [3:8) deg2, [8:15) deg3.
// Traffic floor: 240MB read + 48MB write = 288MB (~36us @ 8TB/s spec).
// R13 = R10 locked in: empirically optimal across 7 tested configs.
//   - 160-row tiles, 9.6KB smem, 128 thr -> 16 blocks/SM = 64 warps (occ max)
//   - block-staged float4 __ldcs loads (evict-first; front-batched MLP=5)
//   - ONE __syncthreads per tile
//   - direct per-row __stcs stores (warp covers 384 contiguous B)
// Measured 41.7us kernel @ 6381 GB/s (80.6% DRAM) — mixed-stream HBM ceiling.

constexpr int THREADS = 128;
constexpr int ROWS_PER_BLOCK = 160;
constexpr int M = 15;
constexpr int NV = ROWS_PER_BLOCK * M / 4;   // 600 float4 in

__global__ __launch_bounds__(THREADS, 16) void l0_contraction_kernel(
    const float* __restrict__ sphc,
    const float* __restrict__ cg,
    float* __restrict__ out,
    int B)
{
    __shared__ float s_in[ROWS_PER_BLOCK * M];   // 9600 B

    const float c0 = __ldg(cg + 0);  // 1/sqrt(3)
    const float c1 = __ldg(cg + 3);  // 1/sqrt(5)
    const float c2 = __ldg(cg + 8);  // 1/sqrt(7)

    const long long row0 = (long long)blockIdx.x * ROWS_PER_BLOCK;
    const int tid = threadIdx.x;
    const int nrows = (int)min((long long)ROWS_PER_BLOCK, (long long)B - row0);

    if (nrows == ROWS_PER_BLOCK) {
        // ---- full tile ----
        // 160 rows * 60B = 9600B per tile; tile base 16B-aligned (9600%16==0).
        const float4* gin = reinterpret_cast<const float4*>(sphc + row0 * M);
        float4* s4 = reinterpret_cast<float4*>(s_in);
        #pragma unroll
        for (int i = 0; i < (NV + THREADS - 1) / THREADS; i++) {  // 5 iters
            const int idx = tid + i * THREADS;
            if (idx < NV) s4[idx] = __ldcs(gin + idx);  // evict-first stream
        }
        __syncthreads();

        // Row tid for all threads; row tid+128 for tid<32.
        {
            const float* x = s_in + tid * M;     // stride 15: conflict-free
            float a = x[0]*x[0] + x[1]*x[1] + x[2]*x[2];
            float b = x[3]*x[3] + x[4]*x[4] + x[5]*x[5] + x[6]*x[6] + x[7]*x[7];
            float c = x[8]*x[8] + x[9]*x[9] + x[10]*x[10] + x[11]*x[11]
                    + x[12]*x[12] + x[13]*x[13] + x[14]*x[14];
            float* o = out + (row0 + tid) * 3;   // warp: 384B contiguous
            __stcs(o + 0, a * c0);
            __stcs(o + 1, b * c1);
            __stcs(o + 2, c * c2);
        }
        if (tid < ROWS_PER_BLOCK - THREADS) {    // tid < 32
            const int r = tid + THREADS;
            const float* x = s_in + r * M;
            float a = x[0]*x[0] + x[1]*x[1] + x[2]*x[2];
            float b = x[3]*x[3] + x[4]*x[4] + x[5]*x[5] + x[6]*x[6] + x[7]*x[7];
            float c = x[8]*x[8] + x[9]*x[9] + x[10]*x[10] + x[11]*x[11]
                    + x[12]*x[12] + x[13]*x[13] + x[14]*x[14];
            float* o = out + (row0 + r) * 3;
            __stcs(o + 0, a * c0);
            __stcs(o + 1, b * c1);
            __stcs(o + 2, c * c2);
        }
    } else {
        // ---- tail tile: scalar, guarded ----
        const float* gin = sphc + row0 * M;
        const int nf = nrows * M;
        for (int i = tid; i < nf; i += THREADS) s_in[i] = gin[i];
        __syncthreads();

        for (int r = tid; r < nrows; r += THREADS) {
            const float* x = s_in + r * M;
            float a = x[0]*x[0] + x[1]*x[1] + x[2]*x[2];
            float b = x[3]*x[3] + x[4]*x[4] + x[5]*x[5] + x[6]*x[6] + x[7]*x[7];
            float c = x[8]*x[8] + x[9]*x[9] + x[10]*x[10] + x[11]*x[11]
                    + x[12]*x[12] + x[13]*x[13] + x[14]*x[14];
            float* o = out + (row0 + r) * 3;
            o[0] = a * c0;
            o[1] = b * c1;
            o[2] = c * c2;
        }
    }
}

extern "C" void kernel_launch(void* const* d_in, const int* in_sizes, int n_in,
                              void* d_out, int out_size) {
    const float* sphc = (const float*)d_in[0];
    const float* cg   = (const float*)d_in[1];
    // d_in[2] = segment_ids (structure is compile-time: 3/5/7 blocks)
    float* out = (float*)d_out;

    const int B = in_sizes[0] / M;  // 4,000,000
    const int grid = (B + ROWS_PER_BLOCK - 1) / ROWS_PER_BLOCK;  // 25000
    l0_contraction_kernel<<<grid, THREADS>>>(sphc, cg, out, B);
}

// round 14
// speedup vs baseline: 1.1483x; 1.1050x over previous
#include <cuda_runtime.h>

// L0 contraction: out[b,n] = cg_n * sum_{m in deg-block n} sphc[b,m]^2
// Row of 15 floats: [0:3) deg1, [3:8) deg2, [8:15) deg3.
// Traffic floor: 240MB read + 48MB write = 288MB (~36us @ 8TB/s spec).
// R14: continue the tile-shrink trend (15.4KB:67% -> 11.5KB:77.7% ->
//      9.6KB:80.6% DRAM). 128-row tiles (7.68KB smem), 128 thr,
//      16 blk/SM = 64 warps. Compute = exactly 1 row/thread (no ragged
//      second pass). Block-staged float4 __ldcs loads, one barrier,
//      direct per-row __stcs stores (warp covers 384 contiguous B).

constexpr int THREADS = 128;
constexpr int ROWS_PER_BLOCK = 128;
constexpr int M = 15;
constexpr int NV = ROWS_PER_BLOCK * M / 4;   // 480 float4 in

__global__ __launch_bounds__(THREADS, 16) void l0_contraction_kernel(
    const float* __restrict__ sphc,
    const float* __restrict__ cg,
    float* __restrict__ out,
    int B)
{
    __shared__ float s_in[ROWS_PER_BLOCK * M];   // 7680 B

    const float c0 = __ldg(cg + 0);  // 1/sqrt(3)
    const float c1 = __ldg(cg + 3);  // 1/sqrt(5)
    const float c2 = __ldg(cg + 8);  // 1/sqrt(7)

    const long long row0 = (long long)blockIdx.x * ROWS_PER_BLOCK;
    const int tid = threadIdx.x;
    const int nrows = (int)min((long long)ROWS_PER_BLOCK, (long long)B - row0);

    if (nrows == ROWS_PER_BLOCK) {
        // ---- full tile ----
        // 128 rows * 60B = 7680B; tile base 16B-aligned (7680%16==0).
        const float4* gin = reinterpret_cast<const float4*>(sphc + row0 * M);
        float4* s4 = reinterpret_cast<float4*>(s_in);
        #pragma unroll
        for (int i = 0; i < (NV + THREADS - 1) / THREADS; i++) {  // 4 iters (last 96 thr)
            const int idx = tid + i * THREADS;
            if (idx < NV) s4[idx] = __ldcs(gin + idx);  // evict-first stream
        }
        __syncthreads();

        // Exactly one row per thread.
        const float* x = s_in + tid * M;         // stride 15: conflict-free
        float a = x[0]*x[0] + x[1]*x[1] + x[2]*x[2];
        float b = x[3]*x[3] + x[4]*x[4] + x[5]*x[5] + x[6]*x[6] + x[7]*x[7];
        float c = x[8]*x[8] + x[9]*x[9] + x[10]*x[10] + x[11]*x[11]
                + x[12]*x[12] + x[13]*x[13] + x[14]*x[14];
        float* o = out + (row0 + tid) * 3;       // warp: 384B contiguous
        __stcs(o + 0, a * c0);
        __stcs(o + 1, b * c1);
        __stcs(o + 2, c * c2);
    } else {
        // ---- tail tile: scalar, guarded ----
        const float* gin = sphc + row0 * M;
        const int nf = nrows * M;
        for (int i = tid; i < nf; i += THREADS) s_in[i] = gin[i];
        __syncthreads();

        for (int r = tid; r < nrows; r += THREADS) {
            const float* x = s_in + r * M;
            float a = x[0]*x[0] + x[1]*x[1] + x[2]*x[2];
            float b = x[3]*x[3] + x[4]*x[4] + x[5]*x[5] + x[6]*x[6] + x[7]*x[7];
            float c = x[8]*x[8] + x[9]*x[9] + x[10]*x[10] + x[11]*x[11]
                    + x[12]*x[12] + x[13]*x[13] + x[14]*x[14];
            float* o = out + (row0 + r) * 3;
            o[0] = a * c0;
            o[1] = b * c1;
            o[2] = c * c2;
        }
    }
}

extern "C" void kernel_launch(void* const* d_in, const int* in_sizes, int n_in,
                              void* d_out, int out_size) {
    const float* sphc = (const float*)d_in[0];
    const float* cg   = (const float*)d_in[1];
    // d_in[2] = segment_ids (structure is compile-time: 3/5/7 blocks)
    float* out = (float*)d_out;

    const int B = in_sizes[0] / M;  // 4,000,000
    const int grid = (B + ROWS_PER_BLOCK - 1) / ROWS_PER_BLOCK;  // 31250
    l0_contraction_kernel<<<grid, THREADS>>>(sphc, cg, out, B);
}